// round 3
// baseline (speedup 1.0000x reference)
#include <cuda_runtime.h>

// Problem constants
#define Bx  8
#define Sx  512
#define Hx  768
#define NHx 12
#define Dx  64
#define Lx  12
#define Mx  (Bx*Sx)       // 4096 rows of activations

// ---------------------------------------------------------------------------
// Scratch (no allocations allowed -> __device__ globals)
// ---------------------------------------------------------------------------
__device__ float g_x [Mx*Hx];
__device__ float g_q [Mx*Hx];
__device__ float g_k [Mx*Hx];
__device__ float g_v [Mx*Hx];
__device__ float g_c [Mx*Hx];
__device__ float g_o1[Mx*Hx];
__device__ float g_h1[Mx*Hx];
__device__ float g_h2[Mx*Hx];
__device__ float g_s [(size_t)Bx*NHx*Sx*Sx];   // attention scores, ~100 MB

// ---------------------------------------------------------------------------
// GEMM: C[4096,768] = A[4096,768] @ W[768,768] + bias (+ optional ReLU)
// 128x128x16 tiling, 256 threads, 8x8 microtile, inner product via
// packed fma.rn.f32x2 (2 FMAs / instruction -> 2x fp32 throughput).
// ---------------------------------------------------------------------------
template<bool RELU>
__global__ __launch_bounds__(256, 2)
void gemm_kernel(const float* __restrict__ A, const float* __restrict__ W,
                 const float* __restrict__ bias, float* __restrict__ C)
{
    const int Kd = Hx, Nd = Hx;
    __shared__ float As[16][128];   // transposed A tile: As[k][m]
    __shared__ float Bs[16][128];   // Bs[k][n]

    const int tid  = threadIdx.x;
    const int bm   = blockIdx.y * 128;
    const int bn   = blockIdx.x * 128;
    const int tr   = tid >> 4;          // 0..15
    const int tc   = tid & 15;          // 0..15
    const int aRow = tid >> 2;          // 0..63
    const int aCol = (tid & 3) << 2;    // 0,4,8,12
    const int bRow = tid >> 5;          // 0..7
    const int bCol = (tid & 31) << 2;   // 0..124

    unsigned long long acc[8][4];       // 8 rows x 4 packed float2 cols
    #pragma unroll
    for (int i = 0; i < 8; ++i)
        #pragma unroll
        for (int j = 0; j < 4; ++j) acc[i][j] = 0ULL;

    const float* Aptr = A + (size_t)bm * Kd;

    for (int k0 = 0; k0 < Kd; k0 += 16) {
        // prefetch gmem into regs
        float4 av0 = *reinterpret_cast<const float4*>(&Aptr[(size_t)(aRow     ) * Kd + k0 + aCol]);
        float4 av1 = *reinterpret_cast<const float4*>(&Aptr[(size_t)(aRow + 64) * Kd + k0 + aCol]);
        float4 bv0 = *reinterpret_cast<const float4*>(&W[(size_t)(k0 + bRow    ) * Nd + bn + bCol]);
        float4 bv1 = *reinterpret_cast<const float4*>(&W[(size_t)(k0 + bRow + 8) * Nd + bn + bCol]);
        __syncthreads();   // previous iteration's compute done before overwrite
        As[aCol+0][aRow]    = av0.x; As[aCol+1][aRow]    = av0.y;
        As[aCol+2][aRow]    = av0.z; As[aCol+3][aRow]    = av0.w;
        As[aCol+0][aRow+64] = av1.x; As[aCol+1][aRow+64] = av1.y;
        As[aCol+2][aRow+64] = av1.z; As[aCol+3][aRow+64] = av1.w;
        *reinterpret_cast<float4*>(&Bs[bRow    ][bCol]) = bv0;
        *reinterpret_cast<float4*>(&Bs[bRow + 8][bCol]) = bv1;
        __syncthreads();

        #pragma unroll
        for (int kk = 0; kk < 16; ++kk) {
            float4 a0 = *reinterpret_cast<const float4*>(&As[kk][tr*8]);
            float4 a1 = *reinterpret_cast<const float4*>(&As[kk][tr*8 + 4]);
            ulonglong2 b0 = *reinterpret_cast<const ulonglong2*>(&Bs[kk][tc*8]);
            ulonglong2 b1 = *reinterpret_cast<const ulonglong2*>(&Bs[kk][tc*8 + 4]);
            unsigned long long bp0 = b0.x, bp1 = b0.y, bp2 = b1.x, bp3 = b1.y;
            float av[8] = {a0.x, a0.y, a0.z, a0.w, a1.x, a1.y, a1.z, a1.w};
            #pragma unroll
            for (int i = 0; i < 8; ++i) {
                unsigned int au = __float_as_uint(av[i]);
                unsigned long long ap;
                asm("mov.b64 %0, {%1, %1};" : "=l"(ap) : "r"(au));
                asm("fma.rn.f32x2 %0, %1, %2, %0;" : "+l"(acc[i][0]) : "l"(ap), "l"(bp0));
                asm("fma.rn.f32x2 %0, %1, %2, %0;" : "+l"(acc[i][1]) : "l"(ap), "l"(bp1));
                asm("fma.rn.f32x2 %0, %1, %2, %0;" : "+l"(acc[i][2]) : "l"(ap), "l"(bp2));
                asm("fma.rn.f32x2 %0, %1, %2, %0;" : "+l"(acc[i][3]) : "l"(ap), "l"(bp3));
            }
        }
    }

    #pragma unroll
    for (int i = 0; i < 8; ++i) {
        const int row = bm + tr*8 + i;
        const int col = bn + tc*8;
        float o[8];
        #pragma unroll
        for (int jp = 0; jp < 4; ++jp) {
            float2 f = *reinterpret_cast<float2*>(&acc[i][jp]);
            o[jp*2 + 0] = f.x + bias[col + jp*2 + 0];
            o[jp*2 + 1] = f.y + bias[col + jp*2 + 1];
        }
        if (RELU) {
            #pragma unroll
            for (int j = 0; j < 8; ++j) o[j] = fmaxf(o[j], 0.0f);
        }
        float4 s0 = make_float4(o[0], o[1], o[2], o[3]);
        float4 s1 = make_float4(o[4], o[5], o[6], o[7]);
        *reinterpret_cast<float4*>(&C[(size_t)row * Nd + col    ]) = s0;
        *reinterpret_cast<float4*>(&C[(size_t)row * Nd + col + 4]) = s1;
    }
}

// ---------------------------------------------------------------------------
// scores[b,h,i,j] = 0.125 * dot(q[b,i,h,:], k[b,j,h,:])   (D = 64)
// 64x64 tile per block, 256 threads, 4x4 microtile.
// ---------------------------------------------------------------------------
__global__ __launch_bounds__(256)
void attn_scores_kernel(const float* __restrict__ Q, const float* __restrict__ Kt,
                        float* __restrict__ S_)
{
    __shared__ float Qs[64][65];
    __shared__ float Ks[64][65];

    const int bh = blockIdx.z;
    const int b  = bh / NHx, h = bh % NHx;
    const int i0 = blockIdx.y << 6;
    const int j0 = blockIdx.x << 6;
    const float* qb = Q  + ((size_t)b * Sx) * Hx + h * Dx;
    const float* kb = Kt + ((size_t)b * Sx) * Hx + h * Dx;

    const int t  = threadIdx.x;
    const int lr = t >> 4;
    const int ld = (t & 15) << 2;
    #pragma unroll
    for (int p = 0; p < 4; ++p) {
        int r = lr + p * 16;
        float4 qv = *reinterpret_cast<const float4*>(&qb[(size_t)(i0 + r) * Hx + ld]);
        float4 kv = *reinterpret_cast<const float4*>(&kb[(size_t)(j0 + r) * Hx + ld]);
        Qs[r][ld+0] = qv.x; Qs[r][ld+1] = qv.y; Qs[r][ld+2] = qv.z; Qs[r][ld+3] = qv.w;
        Ks[r][ld+0] = kv.x; Ks[r][ld+1] = kv.y; Ks[r][ld+2] = kv.z; Ks[r][ld+3] = kv.w;
    }
    __syncthreads();

    const int ty = t >> 4, tx = t & 15;
    float acc[4][4] = {};
    #pragma unroll 4
    for (int d = 0; d < 64; ++d) {
        float qa[4], ka[4];
        #pragma unroll
        for (int ii = 0; ii < 4; ++ii) qa[ii] = Qs[ty*4 + ii][d];
        #pragma unroll
        for (int jj = 0; jj < 4; ++jj) ka[jj] = Ks[tx*4 + jj][d];
        #pragma unroll
        for (int ii = 0; ii < 4; ++ii)
            #pragma unroll
            for (int jj = 0; jj < 4; ++jj)
                acc[ii][jj] += qa[ii] * ka[jj];
    }

    float* sb = S_ + ((size_t)bh * Sx + i0) * Sx + j0;
    #pragma unroll
    for (int ii = 0; ii < 4; ++ii) {
        float4 o = make_float4(acc[ii][0] * 0.125f, acc[ii][1] * 0.125f,
                               acc[ii][2] * 0.125f, acc[ii][3] * 0.125f);
        *reinterpret_cast<float4*>(&sb[(size_t)(ty*4 + ii) * Sx + tx*4]) = o;
    }
}

// ---------------------------------------------------------------------------
// Row softmax over 512 keys. One warp per row, 8 rows per block.
// ---------------------------------------------------------------------------
__global__ __launch_bounds__(256)
void softmax_kernel(float* __restrict__ S_)
{
    const int warp = threadIdx.x >> 5;
    const int lane = threadIdx.x & 31;
    const size_t row = (size_t)blockIdx.x * 8 + warp;
    float* p = S_ + row * Sx;

    float4 v[4];
    #pragma unroll
    for (int k = 0; k < 4; ++k)
        v[k] = *reinterpret_cast<float4*>(&p[lane*4 + k*128]);

    float m = -1e30f;
    #pragma unroll
    for (int k = 0; k < 4; ++k) {
        m = fmaxf(m, fmaxf(fmaxf(v[k].x, v[k].y), fmaxf(v[k].z, v[k].w)));
    }
    #pragma unroll
    for (int o = 16; o; o >>= 1) m = fmaxf(m, __shfl_xor_sync(0xffffffffu, m, o));

    float sum = 0.0f;
    #pragma unroll
    for (int k = 0; k < 4; ++k) {
        v[k].x = __expf(v[k].x - m); v[k].y = __expf(v[k].y - m);
        v[k].z = __expf(v[k].z - m); v[k].w = __expf(v[k].w - m);
        sum += v[k].x + v[k].y + v[k].z + v[k].w;
    }
    #pragma unroll
    for (int o = 16; o; o >>= 1) sum += __shfl_xor_sync(0xffffffffu, sum, o);

    const float r = 1.0f / sum;
    #pragma unroll
    for (int k = 0; k < 4; ++k) {
        v[k].x *= r; v[k].y *= r; v[k].z *= r; v[k].w *= r;
        *reinterpret_cast<float4*>(&p[lane*4 + k*128]) = v[k];
    }
}

// ---------------------------------------------------------------------------
// ctx[b,i,h,d] = sum_j att[b,h,i,j] * v[b,j,h,d]
// Per (b,h): M=512(i) x N=64(d) x K=512(j). Block: 64 i-rows x full 64 d.
// ---------------------------------------------------------------------------
__global__ __launch_bounds__(256)
void attn_ctx_kernel(const float* __restrict__ Att, const float* __restrict__ V,
                     float* __restrict__ C)
{
    __shared__ float As[16][68];   // att transposed: As[j'][i]
    __shared__ float Vs[16][64];   // Vs[j'][d]

    const int bh = blockIdx.y;
    const int b  = bh / NHx, h = bh % NHx;
    const int i0 = blockIdx.x << 6;
    const float* attbase = Att + ((size_t)bh * Sx + i0) * Sx;
    const float* vbase   = V + ((size_t)b * Sx) * Hx + h * Dx;

    const int t  = threadIdx.x;
    const int ty = t >> 4, tx = t & 15;
    const int ar = t >> 2,  ac4 = (t & 3)  << 2;   // att loader: 64 rows x 16 cols
    const int vr = t >> 4,  vc4 = (t & 15) << 2;   // v loader: 16 rows x 64 cols

    float acc[4][4] = {};

    for (int jc = 0; jc < Sx; jc += 16) {
        float4 av = *reinterpret_cast<const float4*>(&attbase[(size_t)ar * Sx + jc + ac4]);
        float4 vv = *reinterpret_cast<const float4*>(&vbase[(size_t)(jc + vr) * Hx + vc4]);
        __syncthreads();
        As[ac4+0][ar] = av.x; As[ac4+1][ar] = av.y;
        As[ac4+2][ar] = av.z; As[ac4+3][ar] = av.w;
        *reinterpret_cast<float4*>(&Vs[vr][vc4]) = vv;
        __syncthreads();

        #pragma unroll
        for (int k = 0; k < 16; ++k) {
            float aa[4];
            #pragma unroll
            for (int ii = 0; ii < 4; ++ii) aa[ii] = As[k][ty*4 + ii];
            float4 vb = *reinterpret_cast<const float4*>(&Vs[k][tx*4]);
            #pragma unroll
            for (int ii = 0; ii < 4; ++ii) {
                acc[ii][0] += aa[ii] * vb.x;
                acc[ii][1] += aa[ii] * vb.y;
                acc[ii][2] += aa[ii] * vb.z;
                acc[ii][3] += aa[ii] * vb.w;
            }
        }
    }

    #pragma unroll
    for (int ii = 0; ii < 4; ++ii) {
        int i = i0 + ty*4 + ii;
        float4 o = make_float4(acc[ii][0], acc[ii][1], acc[ii][2], acc[ii][3]);
        *reinterpret_cast<float4*>(&C[((size_t)(b * Sx + i)) * Hx + h * Dx + tx*4]) = o;
    }
}

// ---------------------------------------------------------------------------
// out = LayerNorm(X + Y) * gamma + beta, eps = 1e-12. One block (256 thr) per row.
// ---------------------------------------------------------------------------
__global__ __launch_bounds__(256)
void add_ln_kernel(const float* __restrict__ X, const float* __restrict__ Y,
                   const float* __restrict__ g, const float* __restrict__ be,
                   float* __restrict__ out)
{
    __shared__ float red[8];
    const int row = blockIdx.x;
    const int t   = threadIdx.x;
    const float* px = X + (size_t)row * Hx;
    const float* py = Y + (size_t)row * Hx;

    float s[3];
    float loc = 0.0f;
    #pragma unroll
    for (int k = 0; k < 3; ++k) {
        int idx = t + k * 256;
        s[k] = px[idx] + py[idx];
        loc += s[k];
    }
    #pragma unroll
    for (int o = 16; o; o >>= 1) loc += __shfl_xor_sync(0xffffffffu, loc, o);
    if ((t & 31) == 0) red[t >> 5] = loc;
    __syncthreads();
    float sum = 0.0f;
    #pragma unroll
    for (int w = 0; w < 8; ++w) sum += red[w];
    const float mean = sum * (1.0f / 768.0f);

    float lv = 0.0f;
    #pragma unroll
    for (int k = 0; k < 3; ++k) {
        float d = s[k] - mean;
        lv += d * d;
    }
    __syncthreads();   // done reading red before reuse
    #pragma unroll
    for (int o = 16; o; o >>= 1) lv += __shfl_xor_sync(0xffffffffu, lv, o);
    if ((t & 31) == 0) red[t >> 5] = lv;
    __syncthreads();
    float var = 0.0f;
    #pragma unroll
    for (int w = 0; w < 8; ++w) var += red[w];
    var *= (1.0f / 768.0f);
    const float inv = rsqrtf(var + 1e-12f);

    float* po = out + (size_t)row * Hx;
    #pragma unroll
    for (int k = 0; k < 3; ++k) {
        int idx = t + k * 256;
        po[idx] = (s[k] - mean) * inv * g[idx] + be[idx];
    }
}

// ---------------------------------------------------------------------------
// Host orchestration: 12 layers, all launches graph-capturable.
// ---------------------------------------------------------------------------
extern "C" void kernel_launch(void* const* d_in, const int* in_sizes, int n_in,
                              void* d_out, int out_size)
{
    const float* x   = (const float*)d_in[0];
    const float* Wq  = (const float*)d_in[1];
    const float* bq  = (const float*)d_in[2];
    const float* Wk  = (const float*)d_in[3];
    const float* bk  = (const float*)d_in[4];
    const float* Wv  = (const float*)d_in[5];
    const float* bv  = (const float*)d_in[6];
    const float* Wo  = (const float*)d_in[7];
    const float* bo  = (const float*)d_in[8];
    const float* g1  = (const float*)d_in[9];
    const float* be1 = (const float*)d_in[10];
    const float* W2  = (const float*)d_in[11];
    const float* b2  = (const float*)d_in[12];
    const float* g2  = (const float*)d_in[13];
    const float* be2 = (const float*)d_in[14];
    float* out = (float*)d_out;

    float *px, *pq, *pk, *pv, *pc, *po1, *ph1, *ph2, *ps;
    cudaGetSymbolAddress((void**)&px,  g_x);
    cudaGetSymbolAddress((void**)&pq,  g_q);
    cudaGetSymbolAddress((void**)&pk,  g_k);
    cudaGetSymbolAddress((void**)&pv,  g_v);
    cudaGetSymbolAddress((void**)&pc,  g_c);
    cudaGetSymbolAddress((void**)&po1, g_o1);
    cudaGetSymbolAddress((void**)&ph1, g_h1);
    cudaGetSymbolAddress((void**)&ph2, g_h2);
    cudaGetSymbolAddress((void**)&ps,  g_s);

    const dim3 gg(Hx / 128, Mx / 128);      // (6, 32) GEMM grid
    const dim3 gs(Sx / 64, Sx / 64, Bx * NHx);  // (8, 8, 96)
    const dim3 gc(Sx / 64, Bx * NHx);           // (8, 96)
    const int softmax_blocks = (Bx * NHx * Sx) / 8;  // 6144

    for (int l = 0; l < Lx; ++l) {
        const float* in = (l == 0) ? x : px;
        const size_t wOff = (size_t)l * Hx * Hx;
        const size_t bOff = (size_t)l * Hx;

        gemm_kernel<false><<<gg, 256>>>(in, Wq + wOff, bq + bOff, pq);
        gemm_kernel<false><<<gg, 256>>>(in, Wk + wOff, bk + bOff, pk);
        gemm_kernel<false><<<gg, 256>>>(in, Wv + wOff, bv + bOff, pv);

        attn_scores_kernel<<<gs, 256>>>(pq, pk, ps);
        softmax_kernel<<<softmax_blocks, 256>>>(ps);
        attn_ctx_kernel<<<gc, 256>>>(ps, pv, pc);

        gemm_kernel<false><<<gg, 256>>>(pc, Wo + wOff, bo + bOff, ph1);
        add_ln_kernel<<<Mx, 256>>>(in, ph1, g1 + bOff, be1 + bOff, po1);

        gemm_kernel<true><<<gg, 256>>>(po1, W2 + wOff, b2 + bOff, ph1);
        gemm_kernel<true><<<gg, 256>>>(ph1, W2 + wOff, b2 + bOff, ph2);

        float* dst = (l == Lx - 1) ? out : px;
        add_ln_kernel<<<Mx, 256>>>(po1, ph2, g2 + bOff, be2 + bOff, dst);
    }
}

// round 8
// speedup vs baseline: 2.5800x; 2.5800x over previous
#include <cuda_runtime.h>
#include <cuda_bf16.h>
#include <cstdint>

// Problem constants
#define Bx  8
#define Sx  512
#define Hx  768
#define NHx 12
#define Dx  64
#define Lx  12
#define Mx  (Bx*Sx)       // 4096 rows of activations
#define WSZ (Hx*Hx)       // 589824 elements per weight matrix

// ---------------------------------------------------------------------------
// Scratch (no allocations allowed -> __device__ globals)
// ---------------------------------------------------------------------------
__device__ float g_x [Mx*Hx];
__device__ float g_q [Mx*Hx];
__device__ float g_k [Mx*Hx];
__device__ float g_v [Mx*Hx];
__device__ float g_c [Mx*Hx];
__device__ float g_o1[Mx*Hx];
__device__ float g_h1[Mx*Hx];
__device__ float g_h2[Mx*Hx];
__device__ float g_s [(size_t)Bx*NHx*Sx*Sx];   // attention scores, ~100 MB

// split-bf16 weight copies: [5 matrices][12 layers][N=768][K=768], K-major (transposed)
__device__ __nv_bfloat16 g_wth[(size_t)5*Lx*WSZ];
__device__ __nv_bfloat16 g_wtl[(size_t)5*Lx*WSZ];
// split-bf16 activation staging
__device__ __nv_bfloat16 g_ahi[(size_t)Mx*Hx];
__device__ __nv_bfloat16 g_alo[(size_t)Mx*Hx];

// ---------------------------------------------------------------------------
// Helpers
// ---------------------------------------------------------------------------
__device__ __forceinline__ uint32_t smem_u32(const void* p) {
    uint32_t a;
    asm("{ .reg .u64 t; cvta.to.shared.u64 t, %1; cvt.u32.u64 %0, t; }" : "=r"(a) : "l"(p));
    return a;
}

__device__ __forceinline__ void cp_async16(uint32_t s, const void* g) {
    asm volatile("cp.async.cg.shared.global [%0], [%1], 16;" :: "r"(s), "l"(g) : "memory");
}
__device__ __forceinline__ void cp_commit() {
    asm volatile("cp.async.commit_group;" ::: "memory");
}

__device__ __forceinline__ void lm_x4(uint32_t* r, uint32_t addr) {
    asm volatile("ldmatrix.sync.aligned.m8n8.x4.shared.b16 {%0,%1,%2,%3}, [%4];"
                 : "=r"(r[0]), "=r"(r[1]), "=r"(r[2]), "=r"(r[3]) : "r"(addr));
}

__device__ __forceinline__ void mma16816(float* d, const uint32_t* a,
                                         uint32_t b0, uint32_t b1) {
    asm volatile(
        "mma.sync.aligned.m16n8k16.row.col.f32.bf16.bf16.f32 "
        "{%0,%1,%2,%3}, {%4,%5,%6,%7}, {%8,%9}, {%0,%1,%2,%3};"
        : "+f"(d[0]), "+f"(d[1]), "+f"(d[2]), "+f"(d[3])
        : "r"(a[0]), "r"(a[1]), "r"(a[2]), "r"(a[3]), "r"(b0), "r"(b1));
}

__device__ __forceinline__ void split_bf16(float a, __nv_bfloat16& hi, __nv_bfloat16& lo) {
    hi = __float2bfloat16(a);
    lo = __float2bfloat16(a - __bfloat162float(hi));
}

// ---------------------------------------------------------------------------
// Weight transpose + split: W[l][k][n] fp32 -> Thi/Tlo[z][n][k] bf16, z = w*12+l
// grid (24, 24, 60), block (32, 8)
// ---------------------------------------------------------------------------
__global__ void wsplit_kernel(const float* __restrict__ Wq, const float* __restrict__ Wk,
                              const float* __restrict__ Wv, const float* __restrict__ Wo,
                              const float* __restrict__ W2,
                              __nv_bfloat16* __restrict__ Thi, __nv_bfloat16* __restrict__ Tlo)
{
    __shared__ float t[32][33];
    const int z = blockIdx.z;
    const int w = z / Lx, l = z % Lx;
    const float* src;
    switch (w) {
        case 0:  src = Wq; break;
        case 1:  src = Wk; break;
        case 2:  src = Wv; break;
        case 3:  src = Wo; break;
        default: src = W2; break;
    }
    src += (size_t)l * WSZ;
    const int n0 = blockIdx.x * 32, k0 = blockIdx.y * 32;

    #pragma unroll
    for (int i = 0; i < 4; ++i) {
        int k = k0 + threadIdx.y + i * 8;
        t[threadIdx.y + i * 8][threadIdx.x] = src[(size_t)k * Hx + n0 + threadIdx.x];
    }
    __syncthreads();

    const int tid = threadIdx.y * 32 + threadIdx.x;
    const int nl = tid >> 3;
    const int kq = (tid & 7) * 4;
    __nv_bfloat16 hi[4], lo[4];
    #pragma unroll
    for (int j = 0; j < 4; ++j) split_bf16(t[kq + j][nl], hi[j], lo[j]);

    __nv_bfloat162 h01 = __halves2bfloat162(hi[0], hi[1]);
    __nv_bfloat162 h23 = __halves2bfloat162(hi[2], hi[3]);
    __nv_bfloat162 l01 = __halves2bfloat162(lo[0], lo[1]);
    __nv_bfloat162 l23 = __halves2bfloat162(lo[2], lo[3]);
    uint2 uh, ul;
    uh.x = *reinterpret_cast<uint32_t*>(&h01); uh.y = *reinterpret_cast<uint32_t*>(&h23);
    ul.x = *reinterpret_cast<uint32_t*>(&l01); ul.y = *reinterpret_cast<uint32_t*>(&l23);

    const size_t o = (size_t)z * WSZ + (size_t)(n0 + nl) * Hx + k0 + kq;
    *reinterpret_cast<uint2*>(&Thi[o]) = uh;
    *reinterpret_cast<uint2*>(&Tlo[o]) = ul;
}

// ---------------------------------------------------------------------------
// Activation split: fp32 [Mx*Hx] -> bf16 hi/lo. grid 3072, block 256
// ---------------------------------------------------------------------------
__global__ void asplit_kernel(const float* __restrict__ A,
                              __nv_bfloat16* __restrict__ Hi, __nv_bfloat16* __restrict__ Lo)
{
    const size_t i = ((size_t)blockIdx.x * 256 + threadIdx.x) * 4;
    float4 v = *reinterpret_cast<const float4*>(A + i);
    __nv_bfloat16 h[4], l[4];
    split_bf16(v.x, h[0], l[0]); split_bf16(v.y, h[1], l[1]);
    split_bf16(v.z, h[2], l[2]); split_bf16(v.w, h[3], l[3]);
    __nv_bfloat162 h01 = __halves2bfloat162(h[0], h[1]);
    __nv_bfloat162 h23 = __halves2bfloat162(h[2], h[3]);
    __nv_bfloat162 l01 = __halves2bfloat162(l[0], l[1]);
    __nv_bfloat162 l23 = __halves2bfloat162(l[2], l[3]);
    uint2 uh, ul;
    uh.x = *reinterpret_cast<uint32_t*>(&h01); uh.y = *reinterpret_cast<uint32_t*>(&h23);
    ul.x = *reinterpret_cast<uint32_t*>(&l01); ul.y = *reinterpret_cast<uint32_t*>(&l23);
    *reinterpret_cast<uint2*>(&Hi[i]) = uh;
    *reinterpret_cast<uint2*>(&Lo[i]) = ul;
}

// ---------------------------------------------------------------------------
// split-bf16 GEMM via mma.sync (base ISA, runs on HMMA pipe):
// C[4096,768] = A @ W + bias (+ReLU)
// CTA 128x128, K-tile 32, 8 warps (each 64x32), 2-stage cp.async pipeline.
// A (hi/lo) bf16 row-major [M,K]; W pre-transposed+split bf16 [N,K] (K-major).
// Products: Ah*Wh + Ah*Wl + Al*Wh  (lo*lo dropped).
// ---------------------------------------------------------------------------
#define ROWB   80                       // padded row stride in bytes (32 bf16 -> 64B + 16B pad)
#define TILEB  (128*ROWB)               // 10240 B, one 128x32 bf16 tile
#define STAGEB (4*TILEB)                // Ahi, Alo, Bhi, Blo
#define GSMEM  (2*STAGEB)               // 81920 B

template<bool RELU>
__global__ __launch_bounds__(256, 2)
void gemm_mma_kernel(const __nv_bfloat16* __restrict__ Ahi,
                     const __nv_bfloat16* __restrict__ Alo,
                     const __nv_bfloat16* __restrict__ Whi,
                     const __nv_bfloat16* __restrict__ Wlo,
                     const float* __restrict__ bias,
                     float* __restrict__ C)
{
    extern __shared__ char smem[];
    const uint32_t sb = smem_u32(smem);

    const int tid    = threadIdx.x;
    const int wid    = tid >> 5;
    const int lane   = tid & 31;
    const int warp_m = wid & 1;          // 0..1  -> 64-row slab
    const int warp_n = wid >> 1;         // 0..3  -> 32-col slab
    const int bm     = blockIdx.y * 128;
    const int bn     = blockIdx.x * 128;

    // per-thread cp.async source/dest offsets (2 rows per thread per tile)
    const int r0 = tid >> 2;             // 0..63
    const int c0 = (tid & 3);            // chunk 0..3 (16B each)
    const uint32_t so0 = (uint32_t)(r0 * ROWB + c0 * 16);
    const uint32_t so1 = (uint32_t)((r0 + 64) * ROWB + c0 * 16);
    const size_t  ga0 = (size_t)(bm + r0)      * Hx + c0 * 8;
    const size_t  ga1 = (size_t)(bm + r0 + 64) * Hx + c0 * 8;
    const size_t  gb0 = (size_t)(bn + r0)      * Hx + c0 * 8;
    const size_t  gb1 = (size_t)(bn + r0 + 64) * Hx + c0 * 8;

    // ldmatrix lane offsets
    const int lrow = lane & 15;
    const uint32_t lkb = (uint32_t)((lane >> 4) << 4);
    const uint32_t a_off = (uint32_t)((warp_m * 64 + lrow) * ROWB) + lkb;   // + mi*16*ROWB + kb
    const uint32_t b_off = (uint32_t)((warp_n * 32 + lrow) * ROWB) + lkb;   // + nj2*16*ROWB + kb

    float acc[4][4][4];
    #pragma unroll
    for (int i = 0; i < 4; ++i)
        #pragma unroll
        for (int j = 0; j < 4; ++j)
            #pragma unroll
            for (int r = 0; r < 4; ++r) acc[i][j][r] = 0.0f;

    // ---- prefetch k-tile 0 into stage 0
    {
        const int k0 = 0;
        const uint32_t st = sb;
        cp_async16(st              + so0, Ahi + ga0 + k0);
        cp_async16(st              + so1, Ahi + ga1 + k0);
        cp_async16(st + 1*TILEB   + so0, Alo + ga0 + k0);
        cp_async16(st + 1*TILEB   + so1, Alo + ga1 + k0);
        cp_async16(st + 2*TILEB   + so0, Whi + gb0 + k0);
        cp_async16(st + 2*TILEB   + so1, Whi + gb1 + k0);
        cp_async16(st + 3*TILEB   + so0, Wlo + gb0 + k0);
        cp_async16(st + 3*TILEB   + so1, Wlo + gb1 + k0);
        cp_commit();
    }

    const int NKT = Hx / 32;   // 24
    for (int kt = 0; kt < NKT; ++kt) {
        if (kt + 1 < NKT) {
            const int k0 = (kt + 1) * 32;
            const uint32_t st = sb + (uint32_t)((kt + 1) & 1) * STAGEB;
            cp_async16(st            + so0, Ahi + ga0 + k0);
            cp_async16(st            + so1, Ahi + ga1 + k0);
            cp_async16(st + 1*TILEB + so0, Alo + ga0 + k0);
            cp_async16(st + 1*TILEB + so1, Alo + ga1 + k0);
            cp_async16(st + 2*TILEB + so0, Whi + gb0 + k0);
            cp_async16(st + 2*TILEB + so1, Whi + gb1 + k0);
            cp_async16(st + 3*TILEB + so0, Wlo + gb0 + k0);
            cp_async16(st + 3*TILEB + so1, Wlo + gb1 + k0);
            cp_commit();
            asm volatile("cp.async.wait_group 1;" ::: "memory");
        } else {
            asm volatile("cp.async.wait_group 0;" ::: "memory");
        }
        __syncthreads();

        const uint32_t st = sb + (uint32_t)(kt & 1) * STAGEB;
        const uint32_t sAh = st;
        const uint32_t sAl = st + 1*TILEB;
        const uint32_t sBh = st + 2*TILEB;
        const uint32_t sBl = st + 3*TILEB;

        #pragma unroll
        for (int k16 = 0; k16 < 2; ++k16) {
            const uint32_t kb = (uint32_t)(k16 * 32);
            uint32_t a[4][4], b[2][4];

            // ---- product 1: Ahi * Whi
            #pragma unroll
            for (int mi = 0; mi < 4; ++mi)
                lm_x4(a[mi], sAh + a_off + (uint32_t)(mi * 16 * ROWB) + kb);
            #pragma unroll
            for (int n2 = 0; n2 < 2; ++n2)
                lm_x4(b[n2], sBh + b_off + (uint32_t)(n2 * 16 * ROWB) + kb);
            #pragma unroll
            for (int mi = 0; mi < 4; ++mi)
                #pragma unroll
                for (int nj = 0; nj < 4; ++nj) {
                    const int n2 = nj >> 1, hi = nj & 1;
                    mma16816(acc[mi][nj], a[mi], b[n2][hi], b[n2][hi + 2]);
                }

            // ---- product 2: Alo * Whi (reload A)
            #pragma unroll
            for (int mi = 0; mi < 4; ++mi)
                lm_x4(a[mi], sAl + a_off + (uint32_t)(mi * 16 * ROWB) + kb);
            #pragma unroll
            for (int mi = 0; mi < 4; ++mi)
                #pragma unroll
                for (int nj = 0; nj < 4; ++nj) {
                    const int n2 = nj >> 1, hi = nj & 1;
                    mma16816(acc[mi][nj], a[mi], b[n2][hi], b[n2][hi + 2]);
                }

            // ---- product 3: Ahi * Wlo (reload both)
            #pragma unroll
            for (int mi = 0; mi < 4; ++mi)
                lm_x4(a[mi], sAh + a_off + (uint32_t)(mi * 16 * ROWB) + kb);
            #pragma unroll
            for (int n2 = 0; n2 < 2; ++n2)
                lm_x4(b[n2], sBl + b_off + (uint32_t)(n2 * 16 * ROWB) + kb);
            #pragma unroll
            for (int mi = 0; mi < 4; ++mi)
                #pragma unroll
                for (int nj = 0; nj < 4; ++nj) {
                    const int n2 = nj >> 1, hi = nj & 1;
                    mma16816(acc[mi][nj], a[mi], b[n2][hi], b[n2][hi + 2]);
                }
        }
        __syncthreads();
    }

    // ---- epilogue: bias (+ReLU), fp32 stores
    const int mrow = bm + warp_m * 64 + (lane >> 2);
    const int ncol = bn + warp_n * 32 + ((lane & 3) << 1);
    #pragma unroll
    for (int mi = 0; mi < 4; ++mi) {
        #pragma unroll
        for (int nj = 0; nj < 4; ++nj) {
            const int col = ncol + nj * 8;
            const float bz0 = __ldg(&bias[col]);
            const float bz1 = __ldg(&bias[col + 1]);
            float2 v0 = make_float2(acc[mi][nj][0] + bz0, acc[mi][nj][1] + bz1);
            float2 v1 = make_float2(acc[mi][nj][2] + bz0, acc[mi][nj][3] + bz1);
            if (RELU) {
                v0.x = fmaxf(v0.x, 0.f); v0.y = fmaxf(v0.y, 0.f);
                v1.x = fmaxf(v1.x, 0.f); v1.y = fmaxf(v1.y, 0.f);
            }
            *reinterpret_cast<float2*>(&C[(size_t)(mrow + mi * 16)     * Hx + col]) = v0;
            *reinterpret_cast<float2*>(&C[(size_t)(mrow + mi * 16 + 8) * Hx + col]) = v1;
        }
    }
}

// ---------------------------------------------------------------------------
// scores[b,h,i,j] = 0.125 * dot(q[b,i,h,:], k[b,j,h,:])   (D = 64)
// ---------------------------------------------------------------------------
__global__ __launch_bounds__(256)
void attn_scores_kernel(const float* __restrict__ Q, const float* __restrict__ Kt,
                        float* __restrict__ S_)
{
    __shared__ float Qs[64][65];
    __shared__ float Ks[64][65];

    const int bh = blockIdx.z;
    const int b  = bh / NHx, h = bh % NHx;
    const int i0 = blockIdx.y << 6;
    const int j0 = blockIdx.x << 6;
    const float* qb = Q  + ((size_t)b * Sx) * Hx + h * Dx;
    const float* kb = Kt + ((size_t)b * Sx) * Hx + h * Dx;

    const int t  = threadIdx.x;
    const int lr = t >> 4;
    const int ld = (t & 15) << 2;
    #pragma unroll
    for (int p = 0; p < 4; ++p) {
        int r = lr + p * 16;
        float4 qv = *reinterpret_cast<const float4*>(&qb[(size_t)(i0 + r) * Hx + ld]);
        float4 kv = *reinterpret_cast<const float4*>(&kb[(size_t)(j0 + r) * Hx + ld]);
        Qs[r][ld+0] = qv.x; Qs[r][ld+1] = qv.y; Qs[r][ld+2] = qv.z; Qs[r][ld+3] = qv.w;
        Ks[r][ld+0] = kv.x; Ks[r][ld+1] = kv.y; Ks[r][ld+2] = kv.z; Ks[r][ld+3] = kv.w;
    }
    __syncthreads();

    const int ty = t >> 4, tx = t & 15;
    float acc[4][4] = {};
    #pragma unroll 4
    for (int d = 0; d < 64; ++d) {
        float qa[4], ka[4];
        #pragma unroll
        for (int ii = 0; ii < 4; ++ii) qa[ii] = Qs[ty*4 + ii][d];
        #pragma unroll
        for (int jj = 0; jj < 4; ++jj) ka[jj] = Ks[tx*4 + jj][d];
        #pragma unroll
        for (int ii = 0; ii < 4; ++ii)
            #pragma unroll
            for (int jj = 0; jj < 4; ++jj)
                acc[ii][jj] += qa[ii] * ka[jj];
    }

    float* sb = S_ + ((size_t)bh * Sx + i0) * Sx + j0;
    #pragma unroll
    for (int ii = 0; ii < 4; ++ii) {
        float4 o = make_float4(acc[ii][0] * 0.125f, acc[ii][1] * 0.125f,
                               acc[ii][2] * 0.125f, acc[ii][3] * 0.125f);
        *reinterpret_cast<float4*>(&sb[(size_t)(ty*4 + ii) * Sx + tx*4]) = o;
    }
}

// ---------------------------------------------------------------------------
// Row softmax over 512 keys. One warp per row, 8 rows per block.
// ---------------------------------------------------------------------------
__global__ __launch_bounds__(256)
void softmax_kernel(float* __restrict__ S_)
{
    const int warp = threadIdx.x >> 5;
    const int lane = threadIdx.x & 31;
    const size_t row = (size_t)blockIdx.x * 8 + warp;
    float* p = S_ + row * Sx;

    float4 v[4];
    #pragma unroll
    for (int k = 0; k < 4; ++k)
        v[k] = *reinterpret_cast<float4*>(&p[lane*4 + k*128]);

    float m = -1e30f;
    #pragma unroll
    for (int k = 0; k < 4; ++k)
        m = fmaxf(m, fmaxf(fmaxf(v[k].x, v[k].y), fmaxf(v[k].z, v[k].w)));
    #pragma unroll
    for (int o = 16; o; o >>= 1) m = fmaxf(m, __shfl_xor_sync(0xffffffffu, m, o));

    float sum = 0.0f;
    #pragma unroll
    for (int k = 0; k < 4; ++k) {
        v[k].x = __expf(v[k].x - m); v[k].y = __expf(v[k].y - m);
        v[k].z = __expf(v[k].z - m); v[k].w = __expf(v[k].w - m);
        sum += v[k].x + v[k].y + v[k].z + v[k].w;
    }
    #pragma unroll
    for (int o = 16; o; o >>= 1) sum += __shfl_xor_sync(0xffffffffu, sum, o);

    const float r = 1.0f / sum;
    #pragma unroll
    for (int k = 0; k < 4; ++k) {
        v[k].x *= r; v[k].y *= r; v[k].z *= r; v[k].w *= r;
        *reinterpret_cast<float4*>(&p[lane*4 + k*128]) = v[k];
    }
}

// ---------------------------------------------------------------------------
// ctx[b,i,h,d] = sum_j att[b,h,i,j] * v[b,j,h,d]
// ---------------------------------------------------------------------------
__global__ __launch_bounds__(256)
void attn_ctx_kernel(const float* __restrict__ Att, const float* __restrict__ V,
                     float* __restrict__ C)
{
    __shared__ float As[16][68];
    __shared__ float Vs[16][64];

    const int bh = blockIdx.y;
    const int b  = bh / NHx, h = bh % NHx;
    const int i0 = blockIdx.x << 6;
    const float* attbase = Att + ((size_t)bh * Sx + i0) * Sx;
    const float* vbase   = V + ((size_t)b * Sx) * Hx + h * Dx;

    const int t  = threadIdx.x;
    const int ty = t >> 4, tx = t & 15;
    const int ar = t >> 2,  ac4 = (t & 3)  << 2;
    const int vr = t >> 4,  vc4 = (t & 15) << 2;

    float acc[4][4] = {};

    for (int jc = 0; jc < Sx; jc += 16) {
        float4 av = *reinterpret_cast<const float4*>(&attbase[(size_t)ar * Sx + jc + ac4]);
        float4 vv = *reinterpret_cast<const float4*>(&vbase[(size_t)(jc + vr) * Hx + vc4]);
        __syncthreads();
        As[ac4+0][ar] = av.x; As[ac4+1][ar] = av.y;
        As[ac4+2][ar] = av.z; As[ac4+3][ar] = av.w;
        *reinterpret_cast<float4*>(&Vs[vr][vc4]) = vv;
        __syncthreads();

        #pragma unroll
        for (int k = 0; k < 16; ++k) {
            float aa[4];
            #pragma unroll
            for (int ii = 0; ii < 4; ++ii) aa[ii] = As[k][ty*4 + ii];
            float4 vb = *reinterpret_cast<const float4*>(&Vs[k][tx*4]);
            #pragma unroll
            for (int ii = 0; ii < 4; ++ii) {
                acc[ii][0] += aa[ii] * vb.x;
                acc[ii][1] += aa[ii] * vb.y;
                acc[ii][2] += aa[ii] * vb.z;
                acc[ii][3] += aa[ii] * vb.w;
            }
        }
    }

    #pragma unroll
    for (int ii = 0; ii < 4; ++ii) {
        int i = i0 + ty*4 + ii;
        float4 o = make_float4(acc[ii][0], acc[ii][1], acc[ii][2], acc[ii][3]);
        *reinterpret_cast<float4*>(&C[((size_t)(b * Sx + i)) * Hx + h * Dx + tx*4]) = o;
    }
}

// ---------------------------------------------------------------------------
// out = LayerNorm(X + Y) * gamma + beta, eps = 1e-12. One block per row.
// ---------------------------------------------------------------------------
__global__ __launch_bounds__(256)
void add_ln_kernel(const float* __restrict__ X, const float* __restrict__ Y,
                   const float* __restrict__ g, const float* __restrict__ be,
                   float* __restrict__ out)
{
    __shared__ float red[8];
    const int row = blockIdx.x;
    const int t   = threadIdx.x;
    const float* px = X + (size_t)row * Hx;
    const float* py = Y + (size_t)row * Hx;

    float s[3];
    float loc = 0.0f;
    #pragma unroll
    for (int k = 0; k < 3; ++k) {
        int idx = t + k * 256;
        s[k] = px[idx] + py[idx];
        loc += s[k];
    }
    #pragma unroll
    for (int o = 16; o; o >>= 1) loc += __shfl_xor_sync(0xffffffffu, loc, o);
    if ((t & 31) == 0) red[t >> 5] = loc;
    __syncthreads();
    float sum = 0.0f;
    #pragma unroll
    for (int w = 0; w < 8; ++w) sum += red[w];
    const float mean = sum * (1.0f / 768.0f);

    float lv = 0.0f;
    #pragma unroll
    for (int k = 0; k < 3; ++k) {
        float d = s[k] - mean;
        lv += d * d;
    }
    __syncthreads();
    #pragma unroll
    for (int o = 16; o; o >>= 1) lv += __shfl_xor_sync(0xffffffffu, lv, o);
    if ((t & 31) == 0) red[t >> 5] = lv;
    __syncthreads();
    float var = 0.0f;
    #pragma unroll
    for (int w = 0; w < 8; ++w) var += red[w];
    var *= (1.0f / 768.0f);
    const float inv = rsqrtf(var + 1e-12f);

    float* po = out + (size_t)row * Hx;
    #pragma unroll
    for (int k = 0; k < 3; ++k) {
        int idx = t + k * 256;
        po[idx] = (s[k] - mean) * inv * g[idx] + be[idx];
    }
}

// ---------------------------------------------------------------------------
// Host orchestration
// ---------------------------------------------------------------------------
extern "C" void kernel_launch(void* const* d_in, const int* in_sizes, int n_in,
                              void* d_out, int out_size)
{
    const float* x   = (const float*)d_in[0];
    const float* Wq  = (const float*)d_in[1];
    const float* bq  = (const float*)d_in[2];
    const float* Wk  = (const float*)d_in[3];
    const float* bk  = (const float*)d_in[4];
    const float* Wv  = (const float*)d_in[5];
    const float* bv  = (const float*)d_in[6];
    const float* Wo  = (const float*)d_in[7];
    const float* bo  = (const float*)d_in[8];
    const float* g1  = (const float*)d_in[9];
    const float* be1 = (const float*)d_in[10];
    const float* W2  = (const float*)d_in[11];
    const float* b2  = (const float*)d_in[12];
    const float* g2  = (const float*)d_in[13];
    const float* be2 = (const float*)d_in[14];
    float* out = (float*)d_out;

    float *px, *pq, *pk, *pv, *pc, *po1, *ph1, *ph2, *ps;
    __nv_bfloat16 *wth, *wtl, *ahi, *alo;
    cudaGetSymbolAddress((void**)&px,  g_x);
    cudaGetSymbolAddress((void**)&pq,  g_q);
    cudaGetSymbolAddress((void**)&pk,  g_k);
    cudaGetSymbolAddress((void**)&pv,  g_v);
    cudaGetSymbolAddress((void**)&pc,  g_c);
    cudaGetSymbolAddress((void**)&po1, g_o1);
    cudaGetSymbolAddress((void**)&ph1, g_h1);
    cudaGetSymbolAddress((void**)&ph2, g_h2);
    cudaGetSymbolAddress((void**)&ps,  g_s);
    cudaGetSymbolAddress((void**)&wth, g_wth);
    cudaGetSymbolAddress((void**)&wtl, g_wtl);
    cudaGetSymbolAddress((void**)&ahi, g_ahi);
    cudaGetSymbolAddress((void**)&alo, g_alo);

    cudaFuncSetAttribute(gemm_mma_kernel<false>,
                         cudaFuncAttributeMaxDynamicSharedMemorySize, GSMEM);
    cudaFuncSetAttribute(gemm_mma_kernel<true>,
                         cudaFuncAttributeMaxDynamicSharedMemorySize, GSMEM);

    // one-time (per replay) weight transpose + bf16 split
    wsplit_kernel<<<dim3(24, 24, 5 * Lx), dim3(32, 8)>>>(Wq, Wk, Wv, Wo, W2, wth, wtl);

    const dim3 gg(Hx / 128, Mx / 128);          // (6, 32)
    const dim3 gs(Sx / 64, Sx / 64, Bx * NHx);  // (8, 8, 96)
    const dim3 gc(Sx / 64, Bx * NHx);           // (8, 96)
    const int split_blocks = (Mx * Hx) / 1024;  // 3072
    const int softmax_blocks = (Bx * NHx * Sx) / 8;

    for (int l = 0; l < Lx; ++l) {
        const float* in = (l == 0) ? x : px;
        const size_t bOff = (size_t)l * Hx;
        const __nv_bfloat16* wq_h = wth + (size_t)(0 * Lx + l) * WSZ;
        const __nv_bfloat16* wq_l = wtl + (size_t)(0 * Lx + l) * WSZ;
        const __nv_bfloat16* wk_h = wth + (size_t)(1 * Lx + l) * WSZ;
        const __nv_bfloat16* wk_l = wtl + (size_t)(1 * Lx + l) * WSZ;
        const __nv_bfloat16* wv_h = wth + (size_t)(2 * Lx + l) * WSZ;
        const __nv_bfloat16* wv_l = wtl + (size_t)(2 * Lx + l) * WSZ;
        const __nv_bfloat16* wo_h = wth + (size_t)(3 * Lx + l) * WSZ;
        const __nv_bfloat16* wo_l = wtl + (size_t)(3 * Lx + l) * WSZ;
        const __nv_bfloat16* w2_h = wth + (size_t)(4 * Lx + l) * WSZ;
        const __nv_bfloat16* w2_l = wtl + (size_t)(4 * Lx + l) * WSZ;

        asplit_kernel<<<split_blocks, 256>>>(in, ahi, alo);
        gemm_mma_kernel<false><<<gg, 256, GSMEM>>>(ahi, alo, wq_h, wq_l, bq + bOff, pq);
        gemm_mma_kernel<false><<<gg, 256, GSMEM>>>(ahi, alo, wk_h, wk_l, bk + bOff, pk);
        gemm_mma_kernel<false><<<gg, 256, GSMEM>>>(ahi, alo, wv_h, wv_l, bv + bOff, pv);

        attn_scores_kernel<<<gs, 256>>>(pq, pk, ps);
        softmax_kernel<<<softmax_blocks, 256>>>(ps);
        attn_ctx_kernel<<<gc, 256>>>(ps, pv, pc);

        asplit_kernel<<<split_blocks, 256>>>(pc, ahi, alo);
        gemm_mma_kernel<false><<<gg, 256, GSMEM>>>(ahi, alo, wo_h, wo_l, bo + bOff, ph1);
        add_ln_kernel<<<Mx, 256>>>(in, ph1, g1 + bOff, be1 + bOff, po1);

        asplit_kernel<<<split_blocks, 256>>>(po1, ahi, alo);
        gemm_mma_kernel<true><<<gg, 256, GSMEM>>>(ahi, alo, w2_h, w2_l, b2 + bOff, ph1);
        asplit_kernel<<<split_blocks, 256>>>(ph1, ahi, alo);
        gemm_mma_kernel<true><<<gg, 256, GSMEM>>>(ahi, alo, w2_h, w2_l, b2 + bOff, ph2);

        float* dst = (l == Lx - 1) ? out : px;
        add_ln_kernel<<<Mx, 256>>>(po1, ph2, g2 + bOff, be2 + bOff, dst);
    }
}